// round 12
// baseline (speedup 1.0000x reference)
#include <cuda_runtime.h>
#include <cstdint>

#define BATCH 4096
#define D0 1024
#define D1 2048
#define D2 2048
#define D3 512
#define NSTEPS 20
#define LRATE 0.1f

// ---------------- device scratch (allocation-free rule: __device__ globals) ----
__device__ __align__(128) float g_r1[BATCH * D1];
__device__ __align__(128) float g_r2[BATCH * D2];
__device__ __align__(128) float g_r3[BATCH * D3];
__device__ __align__(128) float g_e0[BATCH * D0];
__device__ __align__(128) float g_e1[BATCH * D1];
__device__ __align__(128) float g_e2[BATCH * D2];
// tf32-rounded twins (GEMM operands only)
__device__ __align__(128) float g_r1r[BATCH * D1];
__device__ __align__(128) float g_r2r[BATCH * D2];
__device__ __align__(128) float g_r3r[BATCH * D3];
__device__ __align__(128) float g_e0r[BATCH * D0];
__device__ __align__(128) float g_e1r[BATCH * D1];
__device__ __align__(128) float g_e2r[BATCH * D2];
__device__ __align__(128) float g_xr[BATCH * D0];
// rounded weights + rounded transposes (so every GEMM is NT, K-major B)
__device__ __align__(128) float g_W0r[D1 * D0];
__device__ __align__(128) float g_W1r[D2 * D1];
__device__ __align__(128) float g_W2r[D3 * D2];
__device__ __align__(128) float g_W0t[D0 * D1];
__device__ __align__(128) float g_W1t[D1 * D2];
__device__ __align__(128) float g_W2t[D2 * D3];
// double-precision energy accumulator
__device__ double g_esum;

// ---------------- helpers ----------------
__device__ __forceinline__ float rnd_tf32(float x) {
    float y;
    asm("cvt.rna.tf32.f32 %0, %1;" : "=f"(y) : "f"(x));
    return y;
}

__device__ __forceinline__ void mma_tf32(float* c, const uint32_t* a, const uint32_t* b) {
    asm volatile(
        "mma.sync.aligned.m16n8k8.row.col.f32.tf32.tf32.f32 "
        "{%0,%1,%2,%3}, {%4,%5,%6,%7}, {%8,%9}, {%0,%1,%2,%3};"
        : "+f"(c[0]), "+f"(c[1]), "+f"(c[2]), "+f"(c[3])
        : "r"(a[0]), "r"(a[1]), "r"(a[2]), "r"(a[3]), "r"(b[0]), "r"(b[1]));
}

__device__ __forceinline__ void cp16(uint32_t s, const void* g) {
    asm volatile("cp.async.cg.shared.global [%0], [%1], 16;" :: "r"(s), "l"(g));
}

// swizzled float index for element (row, k) in a [128][32] tile
__device__ __forceinline__ int swidx(int row, int k) {
    return (row * 32 + k) ^ ((row & 7) << 2);
}

// ---------------- GEMM config ----------------
constexpr int BM = 128, BN = 128, BK = 32;
constexpr int NTHREADS = 128;                            // 4 warps, 64x64 warp tiles
constexpr int STAGES = 3;
constexpr int STAGE_FLOATS = 2 * BM * BK;                // A tile + B tile = 8192 floats
constexpr int DSMEM = STAGES * STAGE_FLOATS * 4;         // 96 KB

enum { EPI_FWD = 0, EPI_ERR = 1, EPI_UPD = 2 };

// fill one pipeline stage (A tile [BM][BK] + B tile [BN][BK], both K-major gmem)
__device__ __forceinline__ void fill_stage(uint32_t sbase, const float* __restrict__ A,
                                           const float* __restrict__ B, int K,
                                           int bm, int bn, int kt, int tid) {
    const float* Ag = A + (size_t)bm * K + (size_t)kt * BK;
    const float* Bg = B + (size_t)bn * K + (size_t)kt * BK;
#pragma unroll
    for (int i = 0; i < 8; i++) {
        const int c = tid + (i << 7);          // 0..1023 chunk id
        const int row = c >> 3;
        const int kc = (c & 7) << 2;           // k of chunk start
        const uint32_t d = sbase + ((uint32_t)swidx(row, kc) << 2);
        cp16(d, Ag + (size_t)row * K + kc);
    }
#pragma unroll
    for (int i = 0; i < 8; i++) {
        const int c = tid + (i << 7);
        const int row = c >> 3;
        const int kc = (c & 7) << 2;
        const uint32_t d = sbase + (uint32_t)(BM * BK * 4) + ((uint32_t)swidx(row, kc) << 2);
        cp16(d, Bg + (size_t)row * K + kc);
    }
    asm volatile("cp.async.commit_group;" ::: "memory");
}

// shared GEMM body: C(bm:bm+128, bn:bn+128) over K; A,B tf32-rounded, NT K-major.
// 4 warps, each owning a 64x64 output tile (2x2 warp grid).
// Writes full C and rounded twin Cr. If EPI_ERR and esum != nullptr, also
// accumulates sum(C^2) of this tile into *esum (double atomicAdd per CTA).
template <int EPI>
__device__ __forceinline__ void gemm_body(float* smem, uint32_t sb,
                                          const float* __restrict__ A,
                                          const float* __restrict__ B,
                                          const float* __restrict__ X,
                                          float* __restrict__ C,
                                          float* __restrict__ Cr,
                                          double* esum,
                                          int N, int K, int bm, int bn, int tid)
{
    const int wid = tid >> 5;
    const int lane = tid & 31;
    const int gr = lane >> 2;        // 0..7
    const int ct = lane & 3;         // 0..3
    const int wm = (wid & 1) * 64;   // 2 warps down
    const int wn = (wid >> 1) * 64;  // 2 warps across
    const int NT = K / BK;

    float acc[4][8][4];
#pragma unroll
    for (int mi = 0; mi < 4; mi++)
#pragma unroll
        for (int j = 0; j < 8; j++)
#pragma unroll
            for (int q = 0; q < 4; q++) acc[mi][j][q] = 0.0f;

    // prologue: stages 0,1
    fill_stage(sb + 0u * STAGE_FLOATS * 4, A, B, K, bm, bn, 0, tid);
    fill_stage(sb + 1u * STAGE_FLOATS * 4, A, B, K, bm, bn, 1, tid);

    int buf = 0;
    for (int kt = 0; kt < NT; kt++) {
        asm volatile("cp.async.wait_group 1;" ::: "memory");
        __syncthreads();

        const int nf = kt + 2;
        if (nf < NT) {
            int fb = buf + 2; if (fb >= STAGES) fb -= STAGES;
            fill_stage(sb + (uint32_t)fb * STAGE_FLOATS * 4, A, B, K, bm, bn, nf, tid);
        }

        const float* As_ = smem + buf * STAGE_FLOATS;
        const float* Bs_ = As_ + BM * BK;

#pragma unroll
        for (int k8 = 0; k8 < 4; k8++) {
            const int kb = k8 * 8;
            uint32_t afr[4][4];
            uint32_t bfr[8][2];
#pragma unroll
            for (int mi = 0; mi < 4; mi++) {
                const int r0 = wm + mi * 16 + gr;
                afr[mi][0] = __float_as_uint(As_[swidx(r0,     kb + ct)]);
                afr[mi][1] = __float_as_uint(As_[swidx(r0 + 8, kb + ct)]);
                afr[mi][2] = __float_as_uint(As_[swidx(r0,     kb + ct + 4)]);
                afr[mi][3] = __float_as_uint(As_[swidx(r0 + 8, kb + ct + 4)]);
            }
#pragma unroll
            for (int j = 0; j < 8; j++) {
                const int n0 = wn + j * 8 + gr;
                bfr[j][0] = __float_as_uint(Bs_[swidx(n0, kb + ct)]);
                bfr[j][1] = __float_as_uint(Bs_[swidx(n0, kb + ct + 4)]);
            }
#pragma unroll
            for (int mi = 0; mi < 4; mi++)
#pragma unroll
                for (int j = 0; j < 8; j++)
                    mma_tf32(acc[mi][j], afr[mi], bfr[j]);
        }

        buf++; if (buf >= STAGES) buf = 0;
    }

    // ---------------- epilogue ----------------
    float ssq = 0.0f;
#pragma unroll
    for (int mi = 0; mi < 4; mi++) {
#pragma unroll
        for (int half = 0; half < 2; half++) {
            const int m = bm + wm + mi * 16 + gr + half * 8;
#pragma unroll
            for (int j = 0; j < 8; j++) {
                const int n = bn + wn + j * 8 + 2 * ct;
                const size_t off = (size_t)m * N + n;
                const float a0 = acc[mi][j][2 * half + 0];
                const float a1 = acc[mi][j][2 * half + 1];
                float v0, v1;
                if (EPI == EPI_FWD) {
                    v0 = tanhf(a0 + X[n]);
                    v1 = tanhf(a1 + X[n + 1]);
                } else if (EPI == EPI_ERR) {
                    const float2 xv = *(const float2*)(X + off);
                    v0 = xv.x - tanhf(a0);
                    v1 = xv.y - tanhf(a1);
                } else {  // EPI_UPD (covers UPD3 via X == C)
                    const float2 cv = *(const float2*)(C + off);
                    const float2 xv = *(const float2*)(X + off);
                    v0 = cv.x + LRATE * (a0 - xv.x);
                    v1 = cv.y + LRATE * (a1 - xv.y);
                }
                *(float2*)(C + off) = make_float2(v0, v1);
                *(float2*)(Cr + off) = make_float2(rnd_tf32(v0), rnd_tf32(v1));
                if (EPI == EPI_ERR) ssq += v0 * v0 + v1 * v1;
            }
        }
    }

    if (EPI == EPI_ERR && esum != nullptr) {
#pragma unroll
        for (int o = 16; o > 0; o >>= 1) ssq += __shfl_xor_sync(0xFFFFFFFFu, ssq, o);
        __syncthreads();  // stage buffers no longer needed; reuse smem for reduction
        if (lane == 0) smem[wid] = ssq;
        __syncthreads();
        if (tid == 0) {
            float s = 0.0f;
#pragma unroll
            for (int w = 0; w < 4; w++) s += smem[w];
            atomicAdd(esum, (double)s);
        }
    }
}

// single-GEMM kernel (forward pass: sequential dependency)
template <int EPI>
__global__ __launch_bounds__(NTHREADS, 2)
void gemm_epi(const float* __restrict__ A, const float* __restrict__ B,
              const float* __restrict__ X, float* __restrict__ C,
              float* __restrict__ Cr, int N, int K)
{
    extern __shared__ float smem[];
    const uint32_t sb = (uint32_t)__cvta_generic_to_shared(smem);
    gemm_body<EPI>(smem, sb, A, B, X, C, Cr, nullptr, N, K,
                   blockIdx.y * BM, blockIdx.x * BN, threadIdx.x);
}

// ---- fused 3-segment kernel: one launch covers 3 independent GEMMs ----
struct Seg {
    const float* A; const float* B; const float* X;
    float* C; float* Cr;
    int N, K, nbx, cta_end;   // cta_end = exclusive prefix sum of CTA counts
};

template <int EPI>
__global__ __launch_bounds__(NTHREADS, 2)
void gemm_fused3(Seg s0, Seg s1, Seg s2, double* esum)
{
    extern __shared__ float smem[];
    const uint32_t sb = (uint32_t)__cvta_generic_to_shared(smem);
    const int cta = blockIdx.x;

    Seg s;
    int start;
    if (cta < s0.cta_end)       { s = s0; start = 0; }
    else if (cta < s1.cta_end)  { s = s1; start = s0.cta_end; }
    else                        { s = s2; start = s1.cta_end; }

    const int loc = cta - start;
    const int bm = (loc / s.nbx) * BM;
    const int bn = (loc % s.nbx) * BN;
    gemm_body<EPI>(smem, sb, s.A, s.B, s.X, s.C, s.Cr, esum, s.N, s.K, bm, bn, threadIdx.x);
}

// ---------------- prep / output helpers ----------------
__global__ void round_copy(const float* __restrict__ in, float* __restrict__ out, int n) {
    for (int i = blockIdx.x * blockDim.x + threadIdx.x; i < n; i += gridDim.x * blockDim.x)
        out[i] = rnd_tf32(in[i]);
}

// W (Nn,Kk) -> Wr (Nn,Kk) rounded, Wt (Kk,Nn) rounded-transpose
__global__ void trans_round(const float* __restrict__ W, float* __restrict__ Wr,
                            float* __restrict__ Wt, int Nn, int Kk) {
    __shared__ float t[32][33];
    const int k0 = blockIdx.x * 32;
    const int n0 = blockIdx.y * 32;
    const int tx = threadIdx.x;
    const int ty = threadIdx.y;  // 32x8
#pragma unroll
    for (int i = 0; i < 4; i++) {
        const int n = n0 + ty + i * 8;
        const float v = rnd_tf32(W[(size_t)n * Kk + k0 + tx]);
        Wr[(size_t)n * Kk + k0 + tx] = v;
        t[ty + i * 8][tx] = v;
    }
    __syncthreads();
#pragma unroll
    for (int i = 0; i < 4; i++) {
        const int k = k0 + ty + i * 8;
        Wt[(size_t)k * Nn + n0 + tx] = t[tx][ty + i * 8];
    }
}

__global__ void zero_dbl_kernel(double* p) { *p = 0.0; }

// copy r3 -> out while accumulating sum(r3^2) into the double accumulator
__global__ void copy_ssq_kernel(float* __restrict__ dst, const float* __restrict__ src,
                                int n, double* esum) {
    float s = 0.0f;
    for (int i = blockIdx.x * blockDim.x + threadIdx.x; i < n; i += gridDim.x * blockDim.x) {
        const float v = src[i];
        dst[i] = v;
        s += v * v;
    }
#pragma unroll
    for (int o = 16; o > 0; o >>= 1) s += __shfl_xor_sync(0xFFFFFFFFu, s, o);
    __shared__ float ws[32];
    if ((threadIdx.x & 31) == 0) ws[threadIdx.x >> 5] = s;
    __syncthreads();
    if (threadIdx.x < 32) {
        s = (threadIdx.x < (blockDim.x >> 5)) ? ws[threadIdx.x] : 0.0f;
#pragma unroll
        for (int o = 16; o > 0; o >>= 1) s += __shfl_xor_sync(0xFFFFFFFFu, s, o);
        if (threadIdx.x == 0) atomicAdd(esum, (double)s);
    }
}

__global__ void finalize_kernel(const double* esum, float* out) {
    *out = (float)(0.5 * *esum);
}

// ---------------- launcher ----------------
extern "C" void kernel_launch(void* const* d_in, const int* in_sizes, int n_in,
                              void* d_out, int out_size)
{
    const float* x  = (const float*)d_in[0];
    const float* W0 = (const float*)d_in[1];
    const float* b0 = (const float*)d_in[2];
    const float* W1 = (const float*)d_in[3];
    const float* b1 = (const float*)d_in[4];
    const float* W2 = (const float*)d_in[5];
    const float* b2 = (const float*)d_in[6];

    float *r1, *r2, *r3, *e0, *e1, *e2;
    float *r1r, *r2r, *r3r, *e0r, *e1r, *e2r, *xr;
    float *W0r, *W1r, *W2r, *W0t, *W1t, *W2t;
    double* esum;
    cudaGetSymbolAddress((void**)&r1, g_r1);
    cudaGetSymbolAddress((void**)&r2, g_r2);
    cudaGetSymbolAddress((void**)&r3, g_r3);
    cudaGetSymbolAddress((void**)&e0, g_e0);
    cudaGetSymbolAddress((void**)&e1, g_e1);
    cudaGetSymbolAddress((void**)&e2, g_e2);
    cudaGetSymbolAddress((void**)&r1r, g_r1r);
    cudaGetSymbolAddress((void**)&r2r, g_r2r);
    cudaGetSymbolAddress((void**)&r3r, g_r3r);
    cudaGetSymbolAddress((void**)&e0r, g_e0r);
    cudaGetSymbolAddress((void**)&e1r, g_e1r);
    cudaGetSymbolAddress((void**)&e2r, g_e2r);
    cudaGetSymbolAddress((void**)&xr, g_xr);
    cudaGetSymbolAddress((void**)&W0r, g_W0r);
    cudaGetSymbolAddress((void**)&W1r, g_W1r);
    cudaGetSymbolAddress((void**)&W2r, g_W2r);
    cudaGetSymbolAddress((void**)&W0t, g_W0t);
    cudaGetSymbolAddress((void**)&W1t, g_W1t);
    cudaGetSymbolAddress((void**)&W2t, g_W2t);
    cudaGetSymbolAddress((void**)&esum, g_esum);

    cudaFuncSetAttribute(gemm_epi<EPI_FWD>, cudaFuncAttributeMaxDynamicSharedMemorySize, DSMEM);
    cudaFuncSetAttribute(gemm_fused3<EPI_ERR>, cudaFuncAttributeMaxDynamicSharedMemorySize, DSMEM);
    cudaFuncSetAttribute(gemm_fused3<EPI_UPD>, cudaFuncAttributeMaxDynamicSharedMemorySize, DSMEM);

    // ---- prep: round operands to nearest-tf32; transpose weights ----
    round_copy<<<512, 256>>>(x, xr, BATCH * D0);
    {
        dim3 b(32, 8);
        trans_round<<<dim3(D0 / 32, D1 / 32), b>>>(W0, W0r, W0t, D1, D0);
        trans_round<<<dim3(D1 / 32, D2 / 32), b>>>(W1, W1r, W1t, D2, D1);
        trans_round<<<dim3(D2 / 32, D3 / 32), b>>>(W2, W2r, W2t, D3, D2);
    }

    const dim3 blk(NTHREADS);
    const dim3 gD1(D1 / BN, BATCH / BM);
    const dim3 gD2(D2 / BN, BATCH / BM);
    const dim3 gD3(D3 / BN, BATCH / BM);

    // segment CTA counts
    const int MB = BATCH / BM;                       // 32
    const int c_e1 = (D1 / BN) * MB;                 // 512  (K=D2=2048)
    const int c_e0 = (D0 / BN) * MB;                 // 256  (K=D1=2048)
    const int c_e2 = (D2 / BN) * MB;                 // 512  (K=D3=512)
    const int c_r2 = (D2 / BN) * MB;                 // 512  (K=D1=2048)
    const int c_r3 = (D3 / BN) * MB;                 // 128  (K=D2=2048)
    const int c_r1 = (D1 / BN) * MB;                 // 512  (K=D0=1024)

    // ERR group: order long-K first so short-K backfills the tail
    Seg E0 = { r2r, W1t, r1, e1, e1r, D1, D2, D1 / BN, c_e1 };
    Seg E1 = { r1r, W0t, x,  e0, e0r, D0, D1, D0 / BN, c_e1 + c_e0 };
    Seg E2 = { r3r, W2t, r2, e2, e2r, D2, D3, D2 / BN, c_e1 + c_e0 + c_e2 };
    const int nERR = c_e1 + c_e0 + c_e2;

    // UPD group (UPD3 expressed as UPD with X == C == r3)
    Seg U0 = { e1r, W1r, e2, r2, r2r, D2, D1, D2 / BN, c_r2 };
    Seg U1 = { e2r, W2r, r3, r3, r3r, D3, D2, D3 / BN, c_r2 + c_r3 };
    Seg U2 = { e0r, W0r, e1, r1, r1r, D1, D0, D1 / BN, c_r2 + c_r3 + c_r1 };
    const int nUPD = c_r2 + c_r3 + c_r1;

    // ---- forward init: r[i+1] = tanh(r[i] @ W_i^T + b_i) ----
    gemm_epi<EPI_FWD><<<gD1, blk, DSMEM>>>(xr,  W0r, b0, r1, r1r, D1, D0);
    gemm_epi<EPI_FWD><<<gD2, blk, DSMEM>>>(r1r, W1r, b1, r2, r2r, D2, D1);
    gemm_epi<EPI_FWD><<<gD3, blk, DSMEM>>>(r2r, W2r, b2, r3, r3r, D3, D2);

    // ---- relaxation steps: 2 fused launches per step ----
    for (int s = 0; s < NSTEPS; s++) {
        gemm_fused3<EPI_ERR><<<nERR, blk, DSMEM>>>(E0, E1, E2, nullptr);
        gemm_fused3<EPI_UPD><<<nUPD, blk, DSMEM>>>(U0, U1, U2, nullptr);
    }

    // ---- final errors + fused energy accumulation (fp64 accumulator) ----
    float* out = (float*)d_out;
    const int n_r3 = BATCH * D3;
    const bool want_energy = (out_size > n_r3);

    if (want_energy) zero_dbl_kernel<<<1, 1>>>(esum);
    gemm_fused3<EPI_ERR><<<nERR, blk, DSMEM>>>(E0, E1, E2, want_energy ? esum : nullptr);

    // ---- outputs: r3 flattened (+ ssq into esum), then scalar total_error ----
    int ncopy = out_size < n_r3 ? out_size : n_r3;
    copy_ssq_kernel<<<296, 256>>>(out, r3, ncopy, esum);

    if (want_energy) {
        finalize_kernel<<<1, 1>>>(esum, out + n_r3);
    }
}

// round 13
// speedup vs baseline: 1.5030x; 1.5030x over previous
#include <cuda_runtime.h>
#include <cuda_fp16.h>
#include <cstdint>

#define BATCH 4096
#define D0 1024
#define D1 2048
#define D2 2048
#define D3 512
#define NSTEPS 20
#define LRATE 0.1f

// ---------------- device scratch (allocation-free rule: __device__ globals) ----
__device__ __align__(128) float g_r1[BATCH * D1];
__device__ __align__(128) float g_r2[BATCH * D2];
__device__ __align__(128) float g_r3[BATCH * D3];
__device__ __align__(128) float g_e0[BATCH * D0];
__device__ __align__(128) float g_e1[BATCH * D1];
__device__ __align__(128) float g_e2[BATCH * D2];
// fp16-rounded twins (GEMM operands only)
__device__ __align__(128) __half g_r1r[BATCH * D1];
__device__ __align__(128) __half g_r2r[BATCH * D2];
__device__ __align__(128) __half g_r3r[BATCH * D3];
__device__ __align__(128) __half g_e0r[BATCH * D0];
__device__ __align__(128) __half g_e1r[BATCH * D1];
__device__ __align__(128) __half g_e2r[BATCH * D2];
__device__ __align__(128) __half g_xr[BATCH * D0];
// fp16 weights + transposes (so every GEMM is NT, K-major B)
__device__ __align__(128) __half g_W0r[D1 * D0];
__device__ __align__(128) __half g_W1r[D2 * D1];
__device__ __align__(128) __half g_W2r[D3 * D2];
__device__ __align__(128) __half g_W0t[D0 * D1];
__device__ __align__(128) __half g_W1t[D1 * D2];
__device__ __align__(128) __half g_W2t[D2 * D3];
// double-precision energy accumulator
__device__ double g_esum;

// ---------------- helpers ----------------
__device__ __forceinline__ void mma_f16(float* c, const uint32_t* a, const uint32_t* b) {
    asm volatile(
        "mma.sync.aligned.m16n8k16.row.col.f32.f16.f16.f32 "
        "{%0,%1,%2,%3}, {%4,%5,%6,%7}, {%8,%9}, {%0,%1,%2,%3};"
        : "+f"(c[0]), "+f"(c[1]), "+f"(c[2]), "+f"(c[3])
        : "r"(a[0]), "r"(a[1]), "r"(a[2]), "r"(a[3]), "r"(b[0]), "r"(b[1]));
}

#define LDMATRIX_X4(r0, r1, r2, r3, addr) \
    asm volatile("ldmatrix.sync.aligned.m8n8.x4.shared.b16 {%0,%1,%2,%3}, [%4];" \
        : "=r"(r0), "=r"(r1), "=r"(r2), "=r"(r3) : "r"(addr))

__device__ __forceinline__ void cp16(uint32_t s, const void* g) {
    asm volatile("cp.async.cg.shared.global [%0], [%1], 16;" :: "r"(s), "l"(g));
}

// swizzled BYTE offset for (row, 16B-chunk) in a [128 rows][128 B] tile
__device__ __forceinline__ uint32_t swb(int row, int chunk) {
    return (uint32_t)(row * 128 + ((chunk ^ (row & 7)) << 4));
}

// ---------------- GEMM config ----------------
constexpr int BM = 128, BN = 128;
constexpr int BKH = 64;                                  // k-halves per tile (128 B rows)
constexpr int NTHREADS = 256;                            // 8 warps, 32x64 warp tiles
constexpr int STAGES = 3;
constexpr int TILE_BYTES = BM * 128;                     // 16 KB per operand tile
constexpr int STAGE_BYTES = 2 * TILE_BYTES;              // 32 KB
constexpr int DSMEM = STAGES * STAGE_BYTES;              // 96 KB

enum { EPI_FWD = 0, EPI_ERR = 1, EPI_UPD = 2 };

// fill one pipeline stage (A tile [BM][64h] + B tile [BN][64h], both K-major gmem)
__device__ __forceinline__ void fill_stage(uint32_t sbase, const __half* __restrict__ A,
                                           const __half* __restrict__ B, int K,
                                           int bm, int bn, int kt, int tid) {
    const __half* Ag = A + (size_t)bm * K + (size_t)kt * BKH;
    const __half* Bg = B + (size_t)bn * K + (size_t)kt * BKH;
#pragma unroll
    for (int i = 0; i < 4; i++) {
        const int c = tid + (i << 8);          // 0..1023 chunk id
        const int row = c >> 3;
        const int kc = c & 7;                  // 16B chunk within row
        cp16(sbase + swb(row, kc), Ag + (size_t)row * K + kc * 8);
    }
#pragma unroll
    for (int i = 0; i < 4; i++) {
        const int c = tid + (i << 8);
        const int row = c >> 3;
        const int kc = c & 7;
        cp16(sbase + (uint32_t)TILE_BYTES + swb(row, kc), Bg + (size_t)row * K + kc * 8);
    }
    asm volatile("cp.async.commit_group;" ::: "memory");
}

// shared GEMM body: C(bm:bm+128, bn:bn+128) over K; operands fp16, NT K-major.
// Writes full fp32 C and fp16 twin Cr. If EPI_ERR and esum != nullptr, also
// accumulates sum(C^2) of this tile into *esum (double atomicAdd per CTA).
template <int EPI>
__device__ __forceinline__ void gemm_body(float* smem, uint32_t sb,
                                          const __half* __restrict__ A,
                                          const __half* __restrict__ B,
                                          const float* __restrict__ X,
                                          float* __restrict__ C,
                                          __half* __restrict__ Cr,
                                          double* esum,
                                          int N, int K, int bm, int bn, int tid)
{
    const int wid = tid >> 5;
    const int lane = tid & 31;
    const int gr = lane >> 2;        // 0..7
    const int ct = lane & 3;         // 0..3
    const int wm = (wid & 3) * 32;   // 4 warps down
    const int wn = (wid >> 2) * 64;  // 2 warps across
    const int NT = K / BKH;

    const int g  = lane >> 3;        // ldmatrix matrix id 0..3
    const int lr = lane & 7;         // row within matrix

    float acc[2][8][4];
#pragma unroll
    for (int mi = 0; mi < 2; mi++)
#pragma unroll
        for (int j = 0; j < 8; j++)
#pragma unroll
            for (int q = 0; q < 4; q++) acc[mi][j][q] = 0.0f;

    // prologue: stages 0,1
    fill_stage(sb + 0u * STAGE_BYTES, A, B, K, bm, bn, 0, tid);
    fill_stage(sb + 1u * STAGE_BYTES, A, B, K, bm, bn, 1, tid);

    int buf = 0;
    for (int kt = 0; kt < NT; kt++) {
        asm volatile("cp.async.wait_group 1;" ::: "memory");
        __syncthreads();

        const int nf = kt + 2;
        if (nf < NT) {
            int fb = buf + 2; if (fb >= STAGES) fb -= STAGES;
            fill_stage(sb + (uint32_t)fb * STAGE_BYTES, A, B, K, bm, bn, nf, tid);
        }

        const uint32_t Ab = sb + (uint32_t)buf * STAGE_BYTES;
        const uint32_t Bb = Ab + TILE_BYTES;

#pragma unroll
        for (int s = 0; s < 4; s++) {            // four k16 steps per 64-k tile
            // A fragments: 2 x ldmatrix.x4 (matrices: m-lo/k-lo, m-hi/k-lo, m-lo/k-hi, m-hi/k-hi)
            uint32_t afr[2][4];
#pragma unroll
            for (int mi = 0; mi < 2; mi++) {
                const int row = wm + mi * 16 + ((g & 1) << 3) + lr;
                const int chunk = 2 * s + (g >> 1);
                LDMATRIX_X4(afr[mi][0], afr[mi][1], afr[mi][2], afr[mi][3],
                            Ab + swb(row, chunk));
            }
            // B fragments: 4 x ldmatrix.x4 (matrices: j/k-lo, j/k-hi, j+1/k-lo, j+1/k-hi)
            uint32_t bfr[8][2];
#pragma unroll
            for (int p = 0; p < 4; p++) {
                const int row = wn + ((p << 1) + (g >> 1)) * 8 + lr;
                const int chunk = 2 * s + (g & 1);
                LDMATRIX_X4(bfr[2 * p][0], bfr[2 * p][1], bfr[2 * p + 1][0], bfr[2 * p + 1][1],
                            Bb + swb(row, chunk));
            }
#pragma unroll
            for (int mi = 0; mi < 2; mi++)
#pragma unroll
                for (int j = 0; j < 8; j++)
                    mma_f16(acc[mi][j], afr[mi], bfr[j]);
        }

        buf++; if (buf >= STAGES) buf = 0;
    }

    // ---------------- epilogue ----------------
    float ssq = 0.0f;
#pragma unroll
    for (int mi = 0; mi < 2; mi++) {
#pragma unroll
        for (int half = 0; half < 2; half++) {
            const int m = bm + wm + mi * 16 + gr + half * 8;
#pragma unroll
            for (int j = 0; j < 8; j++) {
                const int n = bn + wn + j * 8 + 2 * ct;
                const size_t off = (size_t)m * N + n;
                const float a0 = acc[mi][j][2 * half + 0];
                const float a1 = acc[mi][j][2 * half + 1];
                float v0, v1;
                if (EPI == EPI_FWD) {
                    v0 = tanhf(a0 + X[n]);
                    v1 = tanhf(a1 + X[n + 1]);
                } else if (EPI == EPI_ERR) {
                    const float2 xv = *(const float2*)(X + off);
                    v0 = xv.x - tanhf(a0);
                    v1 = xv.y - tanhf(a1);
                } else {  // EPI_UPD (covers UPD3 via X == C)
                    const float2 cv = *(const float2*)(C + off);
                    const float2 xv = *(const float2*)(X + off);
                    v0 = cv.x + LRATE * (a0 - xv.x);
                    v1 = cv.y + LRATE * (a1 - xv.y);
                }
                *(float2*)(C + off) = make_float2(v0, v1);
                *(__half2*)(Cr + off) = __floats2half2_rn(v0, v1);
                if (EPI == EPI_ERR) ssq += v0 * v0 + v1 * v1;
            }
        }
    }

    if (EPI == EPI_ERR && esum != nullptr) {
#pragma unroll
        for (int o = 16; o > 0; o >>= 1) ssq += __shfl_xor_sync(0xFFFFFFFFu, ssq, o);
        __syncthreads();  // stage buffers no longer needed; reuse smem for reduction
        if (lane == 0) smem[wid] = ssq;
        __syncthreads();
        if (tid == 0) {
            float s = 0.0f;
#pragma unroll
            for (int w = 0; w < 8; w++) s += smem[w];
            atomicAdd(esum, (double)s);
        }
    }
}

// single-GEMM kernel (forward pass: sequential dependency)
template <int EPI>
__global__ __launch_bounds__(NTHREADS, 2)
void gemm_epi(const __half* __restrict__ A, const __half* __restrict__ B,
              const float* __restrict__ X, float* __restrict__ C,
              __half* __restrict__ Cr, int N, int K)
{
    extern __shared__ float smem[];
    const uint32_t sb = (uint32_t)__cvta_generic_to_shared(smem);
    gemm_body<EPI>(smem, sb, A, B, X, C, Cr, nullptr, N, K,
                   blockIdx.y * BM, blockIdx.x * BN, threadIdx.x);
}

// ---- fused 3-segment kernel: one launch covers 3 independent GEMMs ----
struct Seg {
    const __half* A; const __half* B; const float* X;
    float* C; __half* Cr;
    int N, K, nbx, cta_end;   // cta_end = exclusive prefix sum of CTA counts
};

template <int EPI>
__global__ __launch_bounds__(NTHREADS, 2)
void gemm_fused3(Seg s0, Seg s1, Seg s2, double* esum)
{
    extern __shared__ float smem[];
    const uint32_t sb = (uint32_t)__cvta_generic_to_shared(smem);
    const int cta = blockIdx.x;

    Seg s;
    int start;
    if (cta < s0.cta_end)       { s = s0; start = 0; }
    else if (cta < s1.cta_end)  { s = s1; start = s0.cta_end; }
    else                        { s = s2; start = s1.cta_end; }

    const int loc = cta - start;
    const int bm = (loc / s.nbx) * BM;
    const int bn = (loc % s.nbx) * BN;
    gemm_body<EPI>(smem, sb, s.A, s.B, s.X, s.C, s.Cr, esum, s.N, s.K, bm, bn, threadIdx.x);
}

// ---------------- prep / output helpers ----------------
__global__ void round_copy(const float* __restrict__ in, __half* __restrict__ out, int n) {
    for (int i = blockIdx.x * blockDim.x + threadIdx.x; i < n; i += gridDim.x * blockDim.x)
        out[i] = __float2half_rn(in[i]);
}

// W (Nn,Kk) -> Wr (Nn,Kk) fp16, Wt (Kk,Nn) fp16 transpose
__global__ void trans_round(const float* __restrict__ W, __half* __restrict__ Wr,
                            __half* __restrict__ Wt, int Nn, int Kk) {
    __shared__ float t[32][33];
    const int k0 = blockIdx.x * 32;
    const int n0 = blockIdx.y * 32;
    const int tx = threadIdx.x;
    const int ty = threadIdx.y;  // 32x8
#pragma unroll
    for (int i = 0; i < 4; i++) {
        const int n = n0 + ty + i * 8;
        const float v = W[(size_t)n * Kk + k0 + tx];
        Wr[(size_t)n * Kk + k0 + tx] = __float2half_rn(v);
        t[ty + i * 8][tx] = v;
    }
    __syncthreads();
#pragma unroll
    for (int i = 0; i < 4; i++) {
        const int k = k0 + ty + i * 8;
        Wt[(size_t)k * Nn + n0 + tx] = __float2half_rn(t[tx][ty + i * 8]);
    }
}

__global__ void zero_dbl_kernel(double* p) { *p = 0.0; }

// copy r3 -> out while accumulating sum(r3^2) into the double accumulator
__global__ void copy_ssq_kernel(float* __restrict__ dst, const float* __restrict__ src,
                                int n, double* esum) {
    float s = 0.0f;
    for (int i = blockIdx.x * blockDim.x + threadIdx.x; i < n; i += gridDim.x * blockDim.x) {
        const float v = src[i];
        dst[i] = v;
        s += v * v;
    }
#pragma unroll
    for (int o = 16; o > 0; o >>= 1) s += __shfl_xor_sync(0xFFFFFFFFu, s, o);
    __shared__ float ws[32];
    if ((threadIdx.x & 31) == 0) ws[threadIdx.x >> 5] = s;
    __syncthreads();
    if (threadIdx.x < 32) {
        s = (threadIdx.x < (blockDim.x >> 5)) ? ws[threadIdx.x] : 0.0f;
#pragma unroll
        for (int o = 16; o > 0; o >>= 1) s += __shfl_xor_sync(0xFFFFFFFFu, s, o);
        if (threadIdx.x == 0) atomicAdd(esum, (double)s);
    }
}

__global__ void finalize_kernel(const double* esum, float* out) {
    *out = (float)(0.5 * *esum);
}

// ---------------- launcher ----------------
extern "C" void kernel_launch(void* const* d_in, const int* in_sizes, int n_in,
                              void* d_out, int out_size)
{
    const float* x  = (const float*)d_in[0];
    const float* W0 = (const float*)d_in[1];
    const float* b0 = (const float*)d_in[2];
    const float* W1 = (const float*)d_in[3];
    const float* b1 = (const float*)d_in[4];
    const float* W2 = (const float*)d_in[5];
    const float* b2 = (const float*)d_in[6];

    float *r1, *r2, *r3, *e0, *e1, *e2;
    __half *r1r, *r2r, *r3r, *e0r, *e1r, *e2r, *xr;
    __half *W0r, *W1r, *W2r, *W0t, *W1t, *W2t;
    double* esum;
    cudaGetSymbolAddress((void**)&r1, g_r1);
    cudaGetSymbolAddress((void**)&r2, g_r2);
    cudaGetSymbolAddress((void**)&r3, g_r3);
    cudaGetSymbolAddress((void**)&e0, g_e0);
    cudaGetSymbolAddress((void**)&e1, g_e1);
    cudaGetSymbolAddress((void**)&e2, g_e2);
    cudaGetSymbolAddress((void**)&r1r, g_r1r);
    cudaGetSymbolAddress((void**)&r2r, g_r2r);
    cudaGetSymbolAddress((void**)&r3r, g_r3r);
    cudaGetSymbolAddress((void**)&e0r, g_e0r);
    cudaGetSymbolAddress((void**)&e1r, g_e1r);
    cudaGetSymbolAddress((void**)&e2r, g_e2r);
    cudaGetSymbolAddress((void**)&xr, g_xr);
    cudaGetSymbolAddress((void**)&W0r, g_W0r);
    cudaGetSymbolAddress((void**)&W1r, g_W1r);
    cudaGetSymbolAddress((void**)&W2r, g_W2r);
    cudaGetSymbolAddress((void**)&W0t, g_W0t);
    cudaGetSymbolAddress((void**)&W1t, g_W1t);
    cudaGetSymbolAddress((void**)&W2t, g_W2t);
    cudaGetSymbolAddress((void**)&esum, g_esum);

    cudaFuncSetAttribute(gemm_epi<EPI_FWD>, cudaFuncAttributeMaxDynamicSharedMemorySize, DSMEM);
    cudaFuncSetAttribute(gemm_fused3<EPI_ERR>, cudaFuncAttributeMaxDynamicSharedMemorySize, DSMEM);
    cudaFuncSetAttribute(gemm_fused3<EPI_UPD>, cudaFuncAttributeMaxDynamicSharedMemorySize, DSMEM);

    // ---- prep: fp16 operands; transpose weights ----
    round_copy<<<512, 256>>>(x, xr, BATCH * D0);
    {
        dim3 b(32, 8);
        trans_round<<<dim3(D0 / 32, D1 / 32), b>>>(W0, W0r, W0t, D1, D0);
        trans_round<<<dim3(D1 / 32, D2 / 32), b>>>(W1, W1r, W1t, D2, D1);
        trans_round<<<dim3(D2 / 32, D3 / 32), b>>>(W2, W2r, W2t, D3, D2);
    }

    const dim3 blk(NTHREADS);
    const dim3 gD1(D1 / BN, BATCH / BM);
    const dim3 gD2(D2 / BN, BATCH / BM);
    const dim3 gD3(D3 / BN, BATCH / BM);

    // segment CTA counts
    const int MB = BATCH / BM;                       // 32
    const int c_e1 = (D1 / BN) * MB;                 // 512  (K=D2=2048)
    const int c_e0 = (D0 / BN) * MB;                 // 256  (K=D1=2048)
    const int c_e2 = (D2 / BN) * MB;                 // 512  (K=D3=512)
    const int c_r2 = (D2 / BN) * MB;                 // 512  (K=D1=2048)
    const int c_r3 = (D3 / BN) * MB;                 // 128  (K=D2=2048)
    const int c_r1 = (D1 / BN) * MB;                 // 512  (K=D0=1024)

    // ERR group: order long-K first so short-K backfills the tail
    Seg E0 = { r2r, W1t, r1, e1, e1r, D1, D2, D1 / BN, c_e1 };
    Seg E1 = { r1r, W0t, x,  e0, e0r, D0, D1, D0 / BN, c_e1 + c_e0 };
    Seg E2 = { r3r, W2t, r2, e2, e2r, D2, D3, D2 / BN, c_e1 + c_e0 + c_e2 };
    const int nERR = c_e1 + c_e0 + c_e2;

    // UPD group (UPD3 expressed as UPD with X == C == r3)
    Seg U0 = { e1r, W1r, e2, r2, r2r, D2, D1, D2 / BN, c_r2 };
    Seg U1 = { e2r, W2r, r3, r3, r3r, D3, D2, D3 / BN, c_r2 + c_r3 };
    Seg U2 = { e0r, W0r, e1, r1, r1r, D1, D0, D1 / BN, c_r2 + c_r3 + c_r1 };
    const int nUPD = c_r2 + c_r3 + c_r1;

    // ---- forward init: r[i+1] = tanh(r[i] @ W_i^T + b_i) ----
    gemm_epi<EPI_FWD><<<gD1, blk, DSMEM>>>(xr,  W0r, b0, r1, r1r, D1, D0);
    gemm_epi<EPI_FWD><<<gD2, blk, DSMEM>>>(r1r, W1r, b1, r2, r2r, D2, D1);
    gemm_epi<EPI_FWD><<<gD3, blk, DSMEM>>>(r2r, W2r, b2, r3, r3r, D3, D2);

    // ---- relaxation steps: 2 fused launches per step ----
    for (int s = 0; s < NSTEPS; s++) {
        gemm_fused3<EPI_ERR><<<nERR, blk, DSMEM>>>(E0, E1, E2, nullptr);
        gemm_fused3<EPI_UPD><<<nUPD, blk, DSMEM>>>(U0, U1, U2, nullptr);
    }

    // ---- final errors + fused energy accumulation (fp64 accumulator) ----
    float* out = (float*)d_out;
    const int n_r3 = BATCH * D3;
    const bool want_energy = (out_size > n_r3);

    if (want_energy) zero_dbl_kernel<<<1, 1>>>(esum);
    gemm_fused3<EPI_ERR><<<nERR, blk, DSMEM>>>(E0, E1, E2, want_energy ? esum : nullptr);

    // ---- outputs: r3 flattened (+ ssq into esum), then scalar total_error ----
    int ncopy = out_size < n_r3 ? out_size : n_r3;
    copy_ssq_kernel<<<296, 256>>>(out, r3, ncopy, esum);

    if (want_energy) {
        finalize_kernel<<<1, 1>>>(esum, out + n_r3);
    }
}

// round 14
// speedup vs baseline: 1.7229x; 1.1463x over previous
#include <cuda_runtime.h>
#include <cuda_fp16.h>
#include <cstdint>

#define BATCH 4096
#define D0 1024
#define D1 2048
#define D2 2048
#define D3 512
#define NSTEPS 20
#define LRATE 0.1f

// ---------------- device scratch (allocation-free rule: __device__ globals) ----
__device__ __align__(128) float g_r1[BATCH * D1];
__device__ __align__(128) float g_r2[BATCH * D2];
__device__ __align__(128) float g_r3[BATCH * D3];
__device__ __align__(128) float g_e0[BATCH * D0];
__device__ __align__(128) float g_e1[BATCH * D1];
__device__ __align__(128) float g_e2[BATCH * D2];
// fp16-rounded twins (GEMM operands only)
__device__ __align__(128) __half g_r1r[BATCH * D1];
__device__ __align__(128) __half g_r2r[BATCH * D2];
__device__ __align__(128) __half g_r3r[BATCH * D3];
__device__ __align__(128) __half g_e0r[BATCH * D0];
__device__ __align__(128) __half g_e1r[BATCH * D1];
__device__ __align__(128) __half g_e2r[BATCH * D2];
__device__ __align__(128) __half g_xr[BATCH * D0];
// fp16 weights + transposes (so every GEMM is NT, K-major B)
__device__ __align__(128) __half g_W0r[D1 * D0];
__device__ __align__(128) __half g_W1r[D2 * D1];
__device__ __align__(128) __half g_W2r[D3 * D2];
__device__ __align__(128) __half g_W0t[D0 * D1];
__device__ __align__(128) __half g_W1t[D1 * D2];
__device__ __align__(128) __half g_W2t[D2 * D3];
// double-precision energy accumulator
__device__ double g_esum;

// ---------------- helpers ----------------
__device__ __forceinline__ void mma_f16(float* c, const uint32_t* a, const uint32_t* b) {
    asm volatile(
        "mma.sync.aligned.m16n8k16.row.col.f32.f16.f16.f32 "
        "{%0,%1,%2,%3}, {%4,%5,%6,%7}, {%8,%9}, {%0,%1,%2,%3};"
        : "+f"(c[0]), "+f"(c[1]), "+f"(c[2]), "+f"(c[3])
        : "r"(a[0]), "r"(a[1]), "r"(a[2]), "r"(a[3]), "r"(b[0]), "r"(b[1]));
}

#define LDMATRIX_X4(r0, r1, r2, r3, addr) \
    asm volatile("ldmatrix.sync.aligned.m8n8.x4.shared.b16 {%0,%1,%2,%3}, [%4];" \
        : "=r"(r0), "=r"(r1), "=r"(r2), "=r"(r3) : "r"(addr))

__device__ __forceinline__ void cp16(uint32_t s, const void* g) {
    asm volatile("cp.async.cg.shared.global [%0], [%1], 16;" :: "r"(s), "l"(g));
}

// swizzled BYTE offset for (row, 16B-chunk) in a [rows][128 B] tile
__device__ __forceinline__ uint32_t swb(int row, int chunk) {
    return (uint32_t)(row * 128 + ((chunk ^ (row & 7)) << 4));
}

// ---------------- GEMM config ----------------
constexpr int BM = 256, BN = 128;
constexpr int BKH = 64;                                  // k-halves per tile (128 B rows)
constexpr int NTHREADS = 256;                            // 8 warps, 64x64 warp tiles (4x2)
constexpr int STAGES = 4;
constexpr int A_TILE = BM * 128;                         // 32 KB
constexpr int B_TILE = BN * 128;                         // 16 KB
constexpr int STAGE_BYTES = A_TILE + B_TILE;             // 48 KB
constexpr int DSMEM = STAGES * STAGE_BYTES;              // 192 KB

enum { EPI_FWD = 0, EPI_ERR = 1, EPI_UPD = 2 };

// fill one pipeline stage (A tile [BM][64h] + B tile [BN][64h], both K-major gmem)
__device__ __forceinline__ void fill_stage(uint32_t sbase, const __half* __restrict__ A,
                                           const __half* __restrict__ B, int K,
                                           int bm, int bn, int kt, int tid) {
    const __half* Ag = A + (size_t)bm * K + (size_t)kt * BKH;
    const __half* Bg = B + (size_t)bn * K + (size_t)kt * BKH;
#pragma unroll
    for (int i = 0; i < 8; i++) {
        const int c = tid + (i << 8);          // 0..2047 chunk id
        const int row = c >> 3;
        const int kc = c & 7;                  // 16B chunk within row
        cp16(sbase + swb(row, kc), Ag + (size_t)row * K + kc * 8);
    }
#pragma unroll
    for (int i = 0; i < 4; i++) {
        const int c = tid + (i << 8);          // 0..1023
        const int row = c >> 3;
        const int kc = c & 7;
        cp16(sbase + (uint32_t)A_TILE + swb(row, kc), Bg + (size_t)row * K + kc * 8);
    }
    asm volatile("cp.async.commit_group;" ::: "memory");
}

// shared GEMM body: C(bm:bm+256, bn:bn+128) over K; operands fp16, NT K-major.
// 8 warps as 4(down) x 2(across), each owning a 64x64 output tile.
// Writes full fp32 C and fp16 twin Cr. If EPI_ERR and esum != nullptr, also
// accumulates sum(C^2) of this tile into *esum (double atomicAdd per CTA).
template <int EPI>
__device__ __forceinline__ void gemm_body(float* smem, uint32_t sb,
                                          const __half* __restrict__ A,
                                          const __half* __restrict__ B,
                                          const float* __restrict__ X,
                                          float* __restrict__ C,
                                          __half* __restrict__ Cr,
                                          double* esum,
                                          int N, int K, int bm, int bn, int tid)
{
    const int wid = tid >> 5;
    const int lane = tid & 31;
    const int gr = lane >> 2;        // 0..7
    const int ct = lane & 3;         // 0..3
    const int wm = (wid & 3) * 64;   // 4 warps down
    const int wn = (wid >> 2) * 64;  // 2 warps across
    const int NT = K / BKH;

    const int g  = lane >> 3;        // ldmatrix matrix id 0..3
    const int lr = lane & 7;         // row within matrix

    float acc[4][8][4];
#pragma unroll
    for (int mi = 0; mi < 4; mi++)
#pragma unroll
        for (int j = 0; j < 8; j++)
#pragma unroll
            for (int q = 0; q < 4; q++) acc[mi][j][q] = 0.0f;

    // prologue: stages 0,1,2
    fill_stage(sb + 0u * STAGE_BYTES, A, B, K, bm, bn, 0, tid);
    fill_stage(sb + 1u * STAGE_BYTES, A, B, K, bm, bn, 1, tid);
    fill_stage(sb + 2u * STAGE_BYTES, A, B, K, bm, bn, 2, tid);

    int buf = 0;
    for (int kt = 0; kt < NT; kt++) {
        asm volatile("cp.async.wait_group 2;" ::: "memory");
        __syncthreads();

        const int nf = kt + 3;
        if (nf < NT) {
            fill_stage(sb + (uint32_t)((buf + 3) & 3) * STAGE_BYTES, A, B, K, bm, bn, nf, tid);
        }

        const uint32_t Ab = sb + (uint32_t)buf * STAGE_BYTES;
        const uint32_t Bb = Ab + A_TILE;

#pragma unroll
        for (int s = 0; s < 4; s++) {            // four k16 steps per 64-k tile
            // A fragments: 4 x ldmatrix.x4
            uint32_t afr[4][4];
#pragma unroll
            for (int mi = 0; mi < 4; mi++) {
                const int row = wm + mi * 16 + ((g & 1) << 3) + lr;
                const int chunk = 2 * s + (g >> 1);
                LDMATRIX_X4(afr[mi][0], afr[mi][1], afr[mi][2], afr[mi][3],
                            Ab + swb(row, chunk));
            }
            // B fragments: 4 x ldmatrix.x4
            uint32_t bfr[8][2];
#pragma unroll
            for (int p = 0; p < 4; p++) {
                const int row = wn + ((p << 1) + (g >> 1)) * 8 + lr;
                const int chunk = 2 * s + (g & 1);
                LDMATRIX_X4(bfr[2 * p][0], bfr[2 * p][1], bfr[2 * p + 1][0], bfr[2 * p + 1][1],
                            Bb + swb(row, chunk));
            }
#pragma unroll
            for (int mi = 0; mi < 4; mi++)
#pragma unroll
                for (int j = 0; j < 8; j++)
                    mma_f16(acc[mi][j], afr[mi], bfr[j]);
        }

        buf = (buf + 1) & 3;
    }

    // ---------------- epilogue ----------------
    float ssq = 0.0f;
#pragma unroll
    for (int mi = 0; mi < 4; mi++) {
#pragma unroll
        for (int half = 0; half < 2; half++) {
            const int m = bm + wm + mi * 16 + gr + half * 8;
#pragma unroll
            for (int j = 0; j < 8; j++) {
                const int n = bn + wn + j * 8 + 2 * ct;
                const size_t off = (size_t)m * N + n;
                const float a0 = acc[mi][j][2 * half + 0];
                const float a1 = acc[mi][j][2 * half + 1];
                float v0, v1;
                if (EPI == EPI_FWD) {
                    v0 = tanhf(a0 + X[n]);
                    v1 = tanhf(a1 + X[n + 1]);
                } else if (EPI == EPI_ERR) {
                    const float2 xv = *(const float2*)(X + off);
                    v0 = xv.x - tanhf(a0);
                    v1 = xv.y - tanhf(a1);
                } else {  // EPI_UPD (covers UPD3 via X == C)
                    const float2 cv = *(const float2*)(C + off);
                    const float2 xv = *(const float2*)(X + off);
                    v0 = cv.x + LRATE * (a0 - xv.x);
                    v1 = cv.y + LRATE * (a1 - xv.y);
                }
                *(float2*)(C + off) = make_float2(v0, v1);
                *(__half2*)(Cr + off) = __floats2half2_rn(v0, v1);
                if (EPI == EPI_ERR) ssq += v0 * v0 + v1 * v1;
            }
        }
    }

    if (EPI == EPI_ERR && esum != nullptr) {
#pragma unroll
        for (int o = 16; o > 0; o >>= 1) ssq += __shfl_xor_sync(0xFFFFFFFFu, ssq, o);
        __syncthreads();  // stage buffers no longer needed; reuse smem for reduction
        if (lane == 0) smem[wid] = ssq;
        __syncthreads();
        if (tid == 0) {
            float s = 0.0f;
#pragma unroll
            for (int w = 0; w < 8; w++) s += smem[w];
            atomicAdd(esum, (double)s);
        }
    }
}

// single-GEMM kernel (forward pass: sequential dependency)
template <int EPI>
__global__ __launch_bounds__(NTHREADS, 1)
void gemm_epi(const __half* __restrict__ A, const __half* __restrict__ B,
              const float* __restrict__ X, float* __restrict__ C,
              __half* __restrict__ Cr, int N, int K)
{
    extern __shared__ float smem[];
    const uint32_t sb = (uint32_t)__cvta_generic_to_shared(smem);
    gemm_body<EPI>(smem, sb, A, B, X, C, Cr, nullptr, N, K,
                   blockIdx.y * BM, blockIdx.x * BN, threadIdx.x);
}

// ---- fused 3-segment kernel: one launch covers 3 independent GEMMs ----
struct Seg {
    const __half* A; const __half* B; const float* X;
    float* C; __half* Cr;
    int N, K, nbx, cta_end;   // cta_end = exclusive prefix sum of CTA counts
};

template <int EPI>
__global__ __launch_bounds__(NTHREADS, 1)
void gemm_fused3(Seg s0, Seg s1, Seg s2, double* esum)
{
    extern __shared__ float smem[];
    const uint32_t sb = (uint32_t)__cvta_generic_to_shared(smem);
    const int cta = blockIdx.x;

    Seg s;
    int start;
    if (cta < s0.cta_end)       { s = s0; start = 0; }
    else if (cta < s1.cta_end)  { s = s1; start = s0.cta_end; }
    else                        { s = s2; start = s1.cta_end; }

    const int loc = cta - start;
    const int bm = (loc / s.nbx) * BM;
    const int bn = (loc % s.nbx) * BN;
    gemm_body<EPI>(smem, sb, s.A, s.B, s.X, s.C, s.Cr, esum, s.N, s.K, bm, bn, threadIdx.x);
}

// ---------------- prep / output helpers ----------------
__global__ void round_copy(const float* __restrict__ in, __half* __restrict__ out, int n) {
    for (int i = blockIdx.x * blockDim.x + threadIdx.x; i < n; i += gridDim.x * blockDim.x)
        out[i] = __float2half_rn(in[i]);
}

// W (Nn,Kk) -> Wr (Nn,Kk) fp16, Wt (Kk,Nn) fp16 transpose
__global__ void trans_round(const float* __restrict__ W, __half* __restrict__ Wr,
                            __half* __restrict__ Wt, int Nn, int Kk) {
    __shared__ float t[32][33];
    const int k0 = blockIdx.x * 32;
    const int n0 = blockIdx.y * 32;
    const int tx = threadIdx.x;
    const int ty = threadIdx.y;  // 32x8
#pragma unroll
    for (int i = 0; i < 4; i++) {
        const int n = n0 + ty + i * 8;
        const float v = W[(size_t)n * Kk + k0 + tx];
        Wr[(size_t)n * Kk + k0 + tx] = __float2half_rn(v);
        t[ty + i * 8][tx] = v;
    }
    __syncthreads();
#pragma unroll
    for (int i = 0; i < 4; i++) {
        const int k = k0 + ty + i * 8;
        Wt[(size_t)k * Nn + n0 + tx] = __float2half_rn(t[tx][ty + i * 8]);
    }
}

__global__ void zero_dbl_kernel(double* p) { *p = 0.0; }

// copy r3 -> out while accumulating sum(r3^2) into the double accumulator
__global__ void copy_ssq_kernel(float* __restrict__ dst, const float* __restrict__ src,
                                int n, double* esum) {
    float s = 0.0f;
    for (int i = blockIdx.x * blockDim.x + threadIdx.x; i < n; i += gridDim.x * blockDim.x) {
        const float v = src[i];
        dst[i] = v;
        s += v * v;
    }
#pragma unroll
    for (int o = 16; o > 0; o >>= 1) s += __shfl_xor_sync(0xFFFFFFFFu, s, o);
    __shared__ float ws[32];
    if ((threadIdx.x & 31) == 0) ws[threadIdx.x >> 5] = s;
    __syncthreads();
    if (threadIdx.x < 32) {
        s = (threadIdx.x < (blockDim.x >> 5)) ? ws[threadIdx.x] : 0.0f;
#pragma unroll
        for (int o = 16; o > 0; o >>= 1) s += __shfl_xor_sync(0xFFFFFFFFu, s, o);
        if (threadIdx.x == 0) atomicAdd(esum, (double)s);
    }
}

__global__ void finalize_kernel(const double* esum, float* out) {
    *out = (float)(0.5 * *esum);
}

// ---------------- launcher ----------------
extern "C" void kernel_launch(void* const* d_in, const int* in_sizes, int n_in,
                              void* d_out, int out_size)
{
    const float* x  = (const float*)d_in[0];
    const float* W0 = (const float*)d_in[1];
    const float* b0 = (const float*)d_in[2];
    const float* W1 = (const float*)d_in[3];
    const float* b1 = (const float*)d_in[4];
    const float* W2 = (const float*)d_in[5];
    const float* b2 = (const float*)d_in[6];

    float *r1, *r2, *r3, *e0, *e1, *e2;
    __half *r1r, *r2r, *r3r, *e0r, *e1r, *e2r, *xr;
    __half *W0r, *W1r, *W2r, *W0t, *W1t, *W2t;
    double* esum;
    cudaGetSymbolAddress((void**)&r1, g_r1);
    cudaGetSymbolAddress((void**)&r2, g_r2);
    cudaGetSymbolAddress((void**)&r3, g_r3);
    cudaGetSymbolAddress((void**)&e0, g_e0);
    cudaGetSymbolAddress((void**)&e1, g_e1);
    cudaGetSymbolAddress((void**)&e2, g_e2);
    cudaGetSymbolAddress((void**)&r1r, g_r1r);
    cudaGetSymbolAddress((void**)&r2r, g_r2r);
    cudaGetSymbolAddress((void**)&r3r, g_r3r);
    cudaGetSymbolAddress((void**)&e0r, g_e0r);
    cudaGetSymbolAddress((void**)&e1r, g_e1r);
    cudaGetSymbolAddress((void**)&e2r, g_e2r);
    cudaGetSymbolAddress((void**)&xr, g_xr);
    cudaGetSymbolAddress((void**)&W0r, g_W0r);
    cudaGetSymbolAddress((void**)&W1r, g_W1r);
    cudaGetSymbolAddress((void**)&W2r, g_W2r);
    cudaGetSymbolAddress((void**)&W0t, g_W0t);
    cudaGetSymbolAddress((void**)&W1t, g_W1t);
    cudaGetSymbolAddress((void**)&W2t, g_W2t);
    cudaGetSymbolAddress((void**)&esum, g_esum);

    cudaFuncSetAttribute(gemm_epi<EPI_FWD>, cudaFuncAttributeMaxDynamicSharedMemorySize, DSMEM);
    cudaFuncSetAttribute(gemm_fused3<EPI_ERR>, cudaFuncAttributeMaxDynamicSharedMemorySize, DSMEM);
    cudaFuncSetAttribute(gemm_fused3<EPI_UPD>, cudaFuncAttributeMaxDynamicSharedMemorySize, DSMEM);

    // ---- prep: fp16 operands; transpose weights ----
    round_copy<<<512, 256>>>(x, xr, BATCH * D0);
    {
        dim3 b(32, 8);
        trans_round<<<dim3(D0 / 32, D1 / 32), b>>>(W0, W0r, W0t, D1, D0);
        trans_round<<<dim3(D1 / 32, D2 / 32), b>>>(W1, W1r, W1t, D2, D1);
        trans_round<<<dim3(D2 / 32, D3 / 32), b>>>(W2, W2r, W2t, D3, D2);
    }

    const dim3 blk(NTHREADS);
    const dim3 gD1(D1 / BN, BATCH / BM);
    const dim3 gD2(D2 / BN, BATCH / BM);
    const dim3 gD3(D3 / BN, BATCH / BM);

    // segment CTA counts
    const int MB = BATCH / BM;                       // 16
    const int c_e1 = (D1 / BN) * MB;                 // 256  (K=D2=2048)
    const int c_e0 = (D0 / BN) * MB;                 // 128  (K=D1=2048)
    const int c_e2 = (D2 / BN) * MB;                 // 256  (K=D3=512)
    const int c_r2 = (D2 / BN) * MB;                 // 256  (K=D1=2048)
    const int c_r3 = (D3 / BN) * MB;                 // 64   (K=D2=2048)
    const int c_r1 = (D1 / BN) * MB;                 // 256  (K=D0=1024)

    // ERR group: order long-K first so short-K backfills the tail
    Seg E0 = { r2r, W1t, r1, e1, e1r, D1, D2, D1 / BN, c_e1 };
    Seg E1 = { r1r, W0t, x,  e0, e0r, D0, D1, D0 / BN, c_e1 + c_e0 };
    Seg E2 = { r3r, W2t, r2, e2, e2r, D2, D3, D2 / BN, c_e1 + c_e0 + c_e2 };
    const int nERR = c_e1 + c_e0 + c_e2;

    // UPD group (UPD3 expressed as UPD with X == C == r3)
    Seg U0 = { e1r, W1r, e2, r2, r2r, D2, D1, D2 / BN, c_r2 };
    Seg U1 = { e2r, W2r, r3, r3, r3r, D3, D2, D3 / BN, c_r2 + c_r3 };
    Seg U2 = { e0r, W0r, e1, r1, r1r, D1, D0, D1 / BN, c_r2 + c_r3 + c_r1 };
    const int nUPD = c_r2 + c_r3 + c_r1;

    // ---- forward init: r[i+1] = tanh(r[i] @ W_i^T + b_i) ----
    gemm_epi<EPI_FWD><<<gD1, blk, DSMEM>>>(xr,  W0r, b0, r1, r1r, D1, D0);
    gemm_epi<EPI_FWD><<<gD2, blk, DSMEM>>>(r1r, W1r, b1, r2, r2r, D2, D1);
    gemm_epi<EPI_FWD><<<gD3, blk, DSMEM>>>(r2r, W2r, b2, r3, r3r, D3, D2);

    // ---- relaxation steps: 2 fused launches per step ----
    for (int s = 0; s < NSTEPS; s++) {
        gemm_fused3<EPI_ERR><<<nERR, blk, DSMEM>>>(E0, E1, E2, nullptr);
        gemm_fused3<EPI_UPD><<<nUPD, blk, DSMEM>>>(U0, U1, U2, nullptr);
    }

    // ---- final errors + fused energy accumulation (fp64 accumulator) ----
    float* out = (float*)d_out;
    const int n_r3 = BATCH * D3;
    const bool want_energy = (out_size > n_r3);

    if (want_energy) zero_dbl_kernel<<<1, 1>>>(esum);
    gemm_fused3<EPI_ERR><<<nERR, blk, DSMEM>>>(E0, E1, E2, want_energy ? esum : nullptr);

    // ---- outputs: r3 flattened (+ ssq into esum), then scalar total_error ----
    int ncopy = out_size < n_r3 ? out_size : n_r3;
    copy_ssq_kernel<<<296, 256>>>(out, r3, ncopy, esum);

    if (want_energy) {
        finalize_kernel<<<1, 1>>>(esum, out + n_r3);
    }
}